// round 9
// baseline (speedup 1.0000x reference)
#include <cuda_runtime.h>
#include <cstdint>

#define N_MACRO         50000
#define D_FEAT          128
#define SEGS_PER_WARP   4
#define WARPS_PER_BLOCK 8
#define SEGS_PER_BLOCK  (SEGS_PER_WARP * WARPS_PER_BLOCK)   // 32
#define UNROLL          8

// ---------------------------------------------------------------------------
// Single fused kernel.
//   Block b owns segments [b*32, b*32+32).
//   Phase 1: threads 0,1 binary-search the block's window ends (2 searches
//            per block instead of per-warp searches).
//   Phase 2: coalesced transition scan over the window writes all 33 interior
//            lower-bounds into shared memory (each seg_id read once).
//   Phase 3: warp w -> 4 segments; lane owns 4 dims (one LDG.128 per row);
//            8-row batches with node ids fetched by ONE 32B coalesced load +
//            SHFL broadcast (kills the per-row broadcast-load wavefront).
//            Tail = up to two predicated 4-batches (low dup waste).
// ---------------------------------------------------------------------------
__global__ void __launch_bounds__(256, 2)
sp_pool_kernel(const float* __restrict__ feat,
               const int*   __restrict__ node_ids,
               const int*   __restrict__ seg_ids,
               float*       __restrict__ out,
               int n)
{
    __shared__ int s_bounds[SEGS_PER_BLOCK + 1];
    __shared__ int s_ends[2];

    const int tid  = threadIdx.x;
    const int lane = tid & 31;
    const int wid  = tid >> 5;
    const int seg0 = blockIdx.x * SEGS_PER_BLOCK;

    // --- phase 1: window ends via 2 binary searches --------------------------
    if (tid < 2) {
        const int target = seg0 + tid * SEGS_PER_BLOCK;
        int lo = 0, len = n;
        while (len > 0) {
            int half  = len >> 1;
            int probe = lo + half;
            if (__ldg(&seg_ids[probe]) < target) { lo = probe + 1; len -= half + 1; }
            else                                 { len = half; }
        }
        s_ends[tid] = lo;
    }
    __syncthreads();
    const int lo_start = s_ends[0];
    const int lo_end   = s_ends[1];

    // --- phase 2: transition scan fills s_bounds ----------------------------
    if (tid <= SEGS_PER_BLOCK)
        s_bounds[tid] = (tid == 0) ? lo_start : lo_end;
    __syncthreads();

    for (int i = lo_start + tid; i < lo_end; i += blockDim.x) {
        int cur  = __ldg(&seg_ids[i]);
        int prev = (i == 0) ? -1 : __ldg(&seg_ids[i - 1]);
        if (cur != prev) {
            int lo_s = max(prev + 1, seg0);
            int hi_s = min(cur, seg0 + SEGS_PER_BLOCK);
            for (int s = lo_s; s <= hi_s; ++s)
                s_bounds[s - seg0] = i;          // unique writer per s
        }
    }
    __syncthreads();

    // --- phase 3: gather + mean ---------------------------------------------
    const int doff = lane * 4;

    #pragma unroll 1
    for (int g = 0; g < SEGS_PER_WARP; ++g) {
        const int seg = seg0 + wid * SEGS_PER_WARP + g;
        if (seg >= N_MACRO) break;
        const int s0  = s_bounds[wid * SEGS_PER_WARP + g];
        const int s1  = s_bounds[wid * SEGS_PER_WARP + g + 1];
        const int cnt = s1 - s0;

        float4 acc = make_float4(0.f, 0.f, 0.f, 0.f);

        int j = s0;
        // full 8-row batches: 1 coalesced nid load + 8 independent LDG.128
        for (; j + UNROLL <= s1; j += UNROLL) {
            int my_nid = __ldg(&node_ids[j + (lane & 7)]);   // 32B, 1 wavefront
            float4 v[UNROLL];
            #pragma unroll
            for (int k = 0; k < UNROLL; ++k) {
                int nk = __shfl_sync(0xffffffffu, my_nid, k);
                v[k] = *reinterpret_cast<const float4*>(
                    feat + (size_t)nk * D_FEAT + doff);
            }
            #pragma unroll
            for (int k = 0; k < UNROLL; ++k) {
                acc.x += v[k].x; acc.y += v[k].y;
                acc.z += v[k].z; acc.w += v[k].w;
            }
        }
        // tail: up to two predicated 4-batches
        #pragma unroll
        for (int t = 0; t < 2; ++t) {
            if (j < s1) {
                int jc = min(j + (lane & 3), s1 - 1);
                int my_nid = __ldg(&node_ids[jc]);
                float4 v[4]; float w[4];
                #pragma unroll
                for (int k = 0; k < 4; ++k) {
                    int nk = __shfl_sync(0xffffffffu, my_nid, k);
                    w[k]   = (j + k < s1) ? 1.0f : 0.0f;
                    v[k] = *reinterpret_cast<const float4*>(
                        feat + (size_t)nk * D_FEAT + doff);
                }
                #pragma unroll
                for (int k = 0; k < 4; ++k) {
                    acc.x = fmaf(v[k].x, w[k], acc.x);
                    acc.y = fmaf(v[k].y, w[k], acc.y);
                    acc.z = fmaf(v[k].z, w[k], acc.z);
                    acc.w = fmaf(v[k].w, w[k], acc.w);
                }
                j += 4;
            }
        }

        // mean (empty segment -> 0, matching sums / max(counts, 1))
        const float inv = (cnt > 0) ? (1.0f / (float)cnt) : 0.0f;
        float4 r = make_float4(acc.x * inv, acc.y * inv,
                               acc.z * inv, acc.w * inv);
        *reinterpret_cast<float4*>(out + (size_t)seg * D_FEAT + doff) = r;
    }
}

// ---------------------------------------------------------------------------
// Launch
// inputs: node_feature f32 [100000*128], batch_node_ids i32 [n],
//         batch_macro_node_ids i32 [n] (sorted), num_macro_nodes (scalar)
// ---------------------------------------------------------------------------
extern "C" void kernel_launch(void* const* d_in, const int* in_sizes, int n_in,
                              void* d_out, int out_size) {
    const float* feat     = (const float*)d_in[0];
    const int*   node_ids = (const int*)d_in[1];
    const int*   seg_ids  = (const int*)d_in[2];
    float*       out      = (float*)d_out;
    const int n = in_sizes[1];

    const int n_blocks = (N_MACRO + SEGS_PER_BLOCK - 1) / SEGS_PER_BLOCK; // 1563
    sp_pool_kernel<<<n_blocks, 256>>>(feat, node_ids, seg_ids, out, n);
}

// round 10
// speedup vs baseline: 1.3287x; 1.3287x over previous
#include <cuda_runtime.h>
#include <cstdint>

#define N_MACRO       50000
#define D_FEAT        128
#define SEGS_PER_WARP 4
#define UNROLL        8

// lower_bound table: g_bounds[s] = first index i with seg_ids[i] >= s.
// Segment s spans [g_bounds[s], g_bounds[s+1]).
__device__ int g_bounds[N_MACRO + 1];

// ---------------------------------------------------------------------------
// Kernel 1: O(n) boundary detection, int4-vectorized (4 entries / thread).
// (identical to the R6 version that measured fastest overall)
// ---------------------------------------------------------------------------
__global__ void __launch_bounds__(256)
sp_bounds_kernel(const int* __restrict__ seg_ids, int n)
{
    int t  = blockIdx.x * blockDim.x + threadIdx.x;
    int i0 = t * 4;
    if (i0 >= n) return;

    int c0, c1, c2, c3;
    if (i0 + 3 < n) {
        int4 v = *reinterpret_cast<const int4*>(seg_ids + i0);
        c0 = v.x; c1 = v.y; c2 = v.z; c3 = v.w;
    } else {
        c0 = __ldg(&seg_ids[i0]);
        c1 = (i0 + 1 < n) ? __ldg(&seg_ids[i0 + 1]) : c0;
        c2 = (i0 + 2 < n) ? __ldg(&seg_ids[i0 + 2]) : c1;
        c3 = (i0 + 3 < n) ? __ldg(&seg_ids[i0 + 3]) : c2;
    }
    int prev = (i0 == 0) ? -1 : __ldg(&seg_ids[i0 - 1]);

    int cur[4] = {c0, c1, c2, c3};
    #pragma unroll
    for (int k = 0; k < 4; ++k) {
        int idx = i0 + k;
        if (idx < n) {
            for (int s = prev + 1; s <= cur[k]; ++s)
                g_bounds[s] = idx;
            prev = cur[k];
        }
    }
    if (i0 + 4 >= n) {               // last thread closes the table
        for (int s = prev + 1; s <= N_MACRO; ++s)
            g_bounds[s] = n;
    }
}

// ---------------------------------------------------------------------------
// Kernel 2: gather + segment-mean (R6 structure, proven 52.7us).
// Warp owns 4 segments; lane owns 4 dims (one LDG.128 per row); 8-row batch
// keeps 8 independent LDG.128 in flight. ONLY change vs R6: the serial tail
// is replaced by a single predicated 8-batch (clamped index duplicates the
// last row -> L1-hit loads; FMA weight 0 discards them), so MLP stays 8
// through the ragged segment end instead of ~4 serial L2 latencies.
// ---------------------------------------------------------------------------
__global__ void __launch_bounds__(256, 2)
sp_pool_kernel(const float* __restrict__ feat,
               const int*   __restrict__ node_ids,
               float*       __restrict__ out)
{
    const int warp = (blockIdx.x * blockDim.x + threadIdx.x) >> 5;
    const int lane = threadIdx.x & 31;
    const int seg_base = warp * SEGS_PER_WARP;
    if (seg_base >= N_MACRO) return;

    // lanes 0..4 fetch the 5 bounds for this warp's 4 segments
    int b = __ldg(&g_bounds[seg_base + min(lane, SEGS_PER_WARP)]);

    #pragma unroll
    for (int g = 0; g < SEGS_PER_WARP; ++g) {
        const int s0 = __shfl_sync(0xffffffffu, b, g);
        const int s1 = __shfl_sync(0xffffffffu, b, g + 1);
        const int cnt = s1 - s0;

        float4 acc = make_float4(0.f, 0.f, 0.f, 0.f);

        if (cnt > 0) {
            int j = s0;
            // full 8-row batches: 8 independent LDG.128
            for (; j + UNROLL <= s1; j += UNROLL) {
                int nid[UNROLL];
                #pragma unroll
                for (int k = 0; k < UNROLL; ++k)
                    nid[k] = __ldg(&node_ids[j + k]);
                float4 v[UNROLL];
                #pragma unroll
                for (int k = 0; k < UNROLL; ++k)
                    v[k] = *reinterpret_cast<const float4*>(
                        feat + (size_t)nid[k] * D_FEAT + lane * 4);
                #pragma unroll
                for (int k = 0; k < UNROLL; ++k) {
                    acc.x += v[k].x; acc.y += v[k].y;
                    acc.z += v[k].z; acc.w += v[k].w;
                }
            }
            // predicated tail batch: full MLP, dup loads land on one L1 line
            if (j < s1) {
                int   nid[UNROLL];
                float w[UNROLL];
                #pragma unroll
                for (int k = 0; k < UNROLL; ++k) {
                    int jj = j + k;
                    int jc = (jj < s1) ? jj : (s1 - 1);
                    nid[k] = __ldg(&node_ids[jc]);
                    w[k]   = (jj < s1) ? 1.0f : 0.0f;
                }
                float4 v[UNROLL];
                #pragma unroll
                for (int k = 0; k < UNROLL; ++k)
                    v[k] = *reinterpret_cast<const float4*>(
                        feat + (size_t)nid[k] * D_FEAT + lane * 4);
                #pragma unroll
                for (int k = 0; k < UNROLL; ++k) {
                    acc.x = fmaf(v[k].x, w[k], acc.x);
                    acc.y = fmaf(v[k].y, w[k], acc.y);
                    acc.z = fmaf(v[k].z, w[k], acc.z);
                    acc.w = fmaf(v[k].w, w[k], acc.w);
                }
            }
        }

        // mean (empty segment -> 0, matching sums / max(counts, 1))
        const float inv = (cnt > 0) ? (1.0f / (float)cnt) : 0.0f;
        float4 r = make_float4(acc.x * inv, acc.y * inv,
                               acc.z * inv, acc.w * inv);
        *reinterpret_cast<float4*>(
            out + (size_t)(seg_base + g) * D_FEAT + lane * 4) = r;
    }
}

// ---------------------------------------------------------------------------
// Launch
// inputs: node_feature f32 [100000*128], batch_node_ids i32 [n],
//         batch_macro_node_ids i32 [n] (sorted), num_macro_nodes (scalar)
// ---------------------------------------------------------------------------
extern "C" void kernel_launch(void* const* d_in, const int* in_sizes, int n_in,
                              void* d_out, int out_size) {
    const float* feat     = (const float*)d_in[0];
    const int*   node_ids = (const int*)d_in[1];
    const int*   seg_ids  = (const int*)d_in[2];
    float*       out      = (float*)d_out;
    const int n = in_sizes[1];

    if (n > 0) {
        int nt = (n + 3) / 4;
        sp_bounds_kernel<<<(nt + 255) / 256, 256>>>(seg_ids, n);
    }

    const int n_warps  = (N_MACRO + SEGS_PER_WARP - 1) / SEGS_PER_WARP; // 12500
    const int n_blocks = (n_warps * 32 + 255) / 256;                    // 1563
    sp_pool_kernel<<<n_blocks, 256>>>(feat, node_ids, out);
}

// round 11
// speedup vs baseline: 1.3773x; 1.0365x over previous
#include <cuda_runtime.h>
#include <cstdint>

#define N_MACRO       50000
#define D_FEAT        128
#define SEGS_PER_WARP 4
#define UNROLL        8

// ---------------------------------------------------------------------------
// Single fused kernel: gather + segment-mean over sorted segment ids.
//  - warp w owns segments [w*4, w*4+4)
//  - lanes 0..4 find lower_bound(seg_ids, base+lane) via HINT + GALLOP:
//    ids are uniform-random so bound[s] ~ s*n/N_MACRO (sigma ~sqrt(n)/q);
//    gallop (step 256, x4) brackets in <=3 probes, binary on <=4K window.
//    All 5 targets' probes land within ~256 entries of each other -> ~1 line
//    per warp-probe (R8's fused search paid ~9 lines/probe over 21 probes).
//  - gather loop identical to the best-measured (R6, 52.7us) version:
//    lane owns 4 dims, 8-row batch of independent LDG.128, serial tail.
// ---------------------------------------------------------------------------
__global__ void __launch_bounds__(128, 10)
sp_pool_kernel(const float* __restrict__ feat,
               const int*   __restrict__ node_ids,
               const int*   __restrict__ seg_ids,
               float*       __restrict__ out,
               int n)
{
    const int warp = (blockIdx.x * blockDim.x + threadIdx.x) >> 5;
    const int lane = threadIdx.x & 31;
    const int seg_base = warp * SEGS_PER_WARP;
    if (seg_base >= N_MACRO) return;

    // ---- hint + gallop + binary lower_bound (lanes 0..4 meaningful) --------
    const int target = seg_base + min(lane, SEGS_PER_WARP);
    int hint = (int)(((long long)target * (long long)n) / (long long)N_MACRO);
    hint = min(hint, n - 1);

    int l, r;
    if (__ldg(&seg_ids[hint]) < target) {
        // lower_bound > hint: gallop right
        int base = hint, step = 256;
        while (base + step < n && __ldg(&seg_ids[base + step]) < target) {
            base += step; step <<= 2;
        }
        l = base + 1;
        r = min(base + step, n);
    } else {
        // lower_bound <= hint: gallop left
        int top = hint, step = 256;
        while (top - step >= 0 && __ldg(&seg_ids[top - step]) >= target) {
            top -= step; step <<= 2;
        }
        l = (top - step >= 0) ? (top - step + 1) : 0;
        r = top;
    }
    while (l < r) {
        int mid = (l + r) >> 1;
        if (__ldg(&seg_ids[mid]) < target) l = mid + 1;
        else                               r = mid;
    }
    // l == lower_bound(target)

    // ---- gather + mean (R6-proven loop) ------------------------------------
    #pragma unroll
    for (int g = 0; g < SEGS_PER_WARP; ++g) {
        const int s0 = __shfl_sync(0xffffffffu, l, g);
        const int s1 = __shfl_sync(0xffffffffu, l, g + 1);
        const int cnt = s1 - s0;

        float4 acc = make_float4(0.f, 0.f, 0.f, 0.f);

        if (cnt > 0) {
            int j = s0;
            // full 8-row batches: 8 independent LDG.128
            for (; j + UNROLL <= s1; j += UNROLL) {
                int nid[UNROLL];
                #pragma unroll
                for (int k = 0; k < UNROLL; ++k)
                    nid[k] = __ldg(&node_ids[j + k]);
                float4 v[UNROLL];
                #pragma unroll
                for (int k = 0; k < UNROLL; ++k)
                    v[k] = *reinterpret_cast<const float4*>(
                        feat + (size_t)nid[k] * D_FEAT + lane * 4);
                #pragma unroll
                for (int k = 0; k < UNROLL; ++k) {
                    acc.x += v[k].x; acc.y += v[k].y;
                    acc.z += v[k].z; acc.w += v[k].w;
                }
            }
            // serial tail (<=7 rows; hidden by co-resident warps)
            for (; j < s1; ++j) {
                int nid = __ldg(&node_ids[j]);
                float4 v = *reinterpret_cast<const float4*>(
                    feat + (size_t)nid * D_FEAT + lane * 4);
                acc.x += v.x; acc.y += v.y; acc.z += v.z; acc.w += v.w;
            }
        }

        // mean (empty segment -> 0, matching sums / max(counts, 1))
        const float inv = (cnt > 0) ? (1.0f / (float)cnt) : 0.0f;
        float4 rr = make_float4(acc.x * inv, acc.y * inv,
                                acc.z * inv, acc.w * inv);
        *reinterpret_cast<float4*>(
            out + (size_t)(seg_base + g) * D_FEAT + lane * 4) = rr;
    }
}

// ---------------------------------------------------------------------------
// Launch
// inputs: node_feature f32 [100000*128], batch_node_ids i32 [n],
//         batch_macro_node_ids i32 [n] (sorted), num_macro_nodes (scalar)
// ---------------------------------------------------------------------------
extern "C" void kernel_launch(void* const* d_in, const int* in_sizes, int n_in,
                              void* d_out, int out_size) {
    const float* feat     = (const float*)d_in[0];
    const int*   node_ids = (const int*)d_in[1];
    const int*   seg_ids  = (const int*)d_in[2];
    float*       out      = (float*)d_out;
    const int n = in_sizes[1];

    const int n_warps  = (N_MACRO + SEGS_PER_WARP - 1) / SEGS_PER_WARP; // 12500
    const int n_blocks = (n_warps * 32 + 127) / 128;                    // 3125
    sp_pool_kernel<<<n_blocks, 128>>>(feat, node_ids, seg_ids, out, n);
}